// round 9
// baseline (speedup 1.0000x reference)
#include <cuda_runtime.h>
#include <cuda_bf16.h>

// Device-global scratch (no allocations allowed).
__device__ float    g_P[13 * 100];     // CTA partial matrices (80-layer composites)
__device__ float    g_pc[13 * 10];     // CTA partial biases
__device__ float    g_M3[100];         // final composed matrix [out][in] row-major
__device__ float    g_c3[10];          // final composed bias
__device__ unsigned g_ctr;             // arrivals from CTAs 1..12 (self-resetting)

// ---------------------------------------------------------------------------
// Warp-level fold of a chain of n affine maps stored in smem:
//   Wsm: n matrices (row-major [out][in], 100 floats each), bsm: n biases (10).
// Lane j<10 ends holding column j of the composite (m[k] = M[k][j]);
// lane 10 ends holding the composite bias (m[k] = c[k]).
// ---------------------------------------------------------------------------
__device__ __forceinline__ void warp_fold_chain(const float* __restrict__ Wsm,
                                                const float* __restrict__ bsm,
                                                int n, int lane, float m[10]) {
    #pragma unroll
    for (int k = 0; k < 10; ++k)
        m[k] = (lane < 10) ? Wsm[k * 10 + lane] : bsm[k];

    #pragma unroll 1
    for (int s = 1; s < n; ++s) {
        const float2* Wr = (const float2*)(Wsm + s * 100);
        float acc[10];
        #pragma unroll
        for (int i = 0; i < 10; ++i) {
            const float2 w0 = Wr[i * 5 + 0];
            const float2 w1 = Wr[i * 5 + 1];
            const float2 w2 = Wr[i * 5 + 2];
            const float2 w3 = Wr[i * 5 + 3];
            const float2 w4 = Wr[i * 5 + 4];
            float a;
            a = w0.x * m[0];
            a = fmaf(w0.y, m[1], a);
            a = fmaf(w1.x, m[2], a);
            a = fmaf(w1.y, m[3], a);
            a = fmaf(w2.x, m[4], a);
            a = fmaf(w2.y, m[5], a);
            a = fmaf(w3.x, m[6], a);
            a = fmaf(w3.y, m[7], a);
            a = fmaf(w4.x, m[8], a);
            a = fmaf(w4.y, m[9], a);
            acc[i] = a;
        }
        if (lane == 10) {
            #pragma unroll
            for (int i = 0; i < 10; ++i) acc[i] += bsm[s * 10 + i];
        }
        #pragma unroll
        for (int i = 0; i < 10; ++i) m[i] = acc[i];
    }
}

__device__ __forceinline__ void warp_copy4(float* dst, const float* src,
                                           int nfloats, int lane) {
    const float4* s4 = (const float4*)src;
    float4* d4 = (float4*)dst;
    for (int i = lane; i < nfloats / 4; i += 32) d4[i] = s4[i];
}

// ---------------------------------------------------------------------------
// fold_kernel (grid = 13 x 256): composes the 1000 affine maps into one.
//   warp w of CTA c folds chunk c*8+w (10 layers, smem-staged);
//   warp 0 folds the CTA's 8 (or 4) chunk partials -> g_P[c];
//   CTA 0 waits for 12 arrivals, warp 0 folds the 13 partials -> g_M3/g_c3.
// ---------------------------------------------------------------------------
__global__ void __launch_bounds__(256) fold_kernel(const float* __restrict__ Ws,
                                                   const float* __restrict__ bs) {
    __shared__ float SLOT[8][1104];   // per-warp chunk scratch (1000 W + 100 b)
    __shared__ float PW[13 * 100];    // partial matrices (local reduce / final)
    __shared__ float Pb[13 * 10];     // partial biases

    const int tid  = threadIdx.x;
    const int lane = tid & 31;
    const int warp = tid >> 5;
    const int cta  = blockIdx.x;

    // ---- Level 1: warp folds its 10-layer chunk ----
    const int chunk = cta * 8 + warp;
    if (chunk < 100) {
        warp_copy4(SLOT[warp],        Ws + (size_t)chunk * 1000, 1000, lane);
        warp_copy4(SLOT[warp] + 1000, bs + (size_t)chunk * 100,  100,  lane);
        __syncwarp();
        float m[10];
        warp_fold_chain(SLOT[warp], SLOT[warp] + 1000, 10, lane, m);
        if (lane < 10) {
            #pragma unroll
            for (int k = 0; k < 10; ++k) PW[warp * 100 + k * 10 + lane] = m[k];
        } else if (lane == 10) {
            #pragma unroll
            for (int k = 0; k < 10; ++k) Pb[warp * 10 + k] = m[k];
        }
    }
    __syncthreads();

    // ---- Level 2: warp 0 folds the CTA's chunk partials in order ----
    const int nw = (cta < 12) ? 8 : 4;
    if (warp == 0) {
        float m[10];
        warp_fold_chain(PW, Pb, nw, lane, m);
        if (lane < 10) {
            #pragma unroll
            for (int k = 0; k < 10; ++k) g_P[cta * 100 + k * 10 + lane] = m[k];
        } else if (lane == 10) {
            #pragma unroll
            for (int k = 0; k < 10; ++k) g_pc[cta * 10 + k] = m[k];
        }
    }
    __threadfence();
    __syncthreads();

    if (cta != 0) {
        if (tid == 0) atomicAdd(&g_ctr, 1u);
        return;
    }

    // ---- Level 3 (CTA 0): wait for the other 12, fold the 13 partials ----
    if (tid == 0) {
        while (*(volatile unsigned*)&g_ctr < 12u) __nanosleep(32);
    }
    __syncthreads();
    __threadfence();   // acquire

    for (int i = tid; i < 1300; i += 256) PW[i] = g_P[i];
    for (int i = tid; i < 130;  i += 256) Pb[i] = g_pc[i];
    __syncthreads();

    if (warp == 0) {
        float m[10];
        warp_fold_chain(PW, Pb, 13, lane, m);
        if (lane < 10) {
            #pragma unroll
            for (int k = 0; k < 10; ++k) g_M3[k * 10 + lane] = m[k];
        } else if (lane == 10) {
            #pragma unroll
            for (int k = 0; k < 10; ++k) g_c3[k] = m[k];
        }
    }
    if (tid == 0) g_ctr = 0;   // replay-safe reset (after final use)
}

// ---------------------------------------------------------------------------
// PTX helpers (cp.async.bulk 1D + mbarrier + packed f32x2 FMA).
// ---------------------------------------------------------------------------
__device__ __forceinline__ unsigned smem_u32(const void* p) {
    unsigned r;
    asm("{ .reg .u64 t; cvta.to.shared.u64 t, %1; cvt.u32.u64 %0, t; }"
        : "=r"(r) : "l"(p));
    return r;
}
__device__ __forceinline__ void mbar_init(unsigned addr, unsigned count) {
    asm volatile("mbarrier.init.shared.b64 [%0], %1;" :: "r"(addr), "r"(count) : "memory");
}
__device__ __forceinline__ void mbar_expect_tx(unsigned addr, unsigned bytes) {
    asm volatile("mbarrier.arrive.expect_tx.shared.b64 _, [%0], %1;"
                 :: "r"(addr), "r"(bytes) : "memory");
}
__device__ __forceinline__ void bulk_load(unsigned dst_smem, const void* src_gmem,
                                          unsigned bytes, unsigned mbar) {
    asm volatile("cp.async.bulk.shared::cta.global.mbarrier::complete_tx::bytes "
                 "[%0], [%1], %2, [%3];"
                 :: "r"(dst_smem), "l"(src_gmem), "r"(bytes), "r"(mbar) : "memory");
}
__device__ __forceinline__ void mbar_wait(unsigned addr, unsigned parity) {
    unsigned done;
    asm volatile("{\n\t.reg .pred p;\n\t"
                 "mbarrier.try_wait.parity.acquire.cta.shared::cta.b64 p, [%1], %2;\n\t"
                 "selp.b32 %0, 1, 0, p;\n\t}"
                 : "=r"(done) : "r"(addr), "r"(parity) : "memory");
    while (!done) {
        asm volatile("{\n\t.reg .pred p;\n\t"
                     "mbarrier.try_wait.parity.acquire.cta.shared::cta.b64 p, [%1], %2, 0x989680;\n\t"
                     "selp.b32 %0, 1, 0, p;\n\t}"
                     : "=r"(done) : "r"(addr), "r"(parity) : "memory");
    }
}
__device__ __forceinline__ unsigned long long pack2(float lo, float hi) {
    unsigned long long r;
    asm("mov.b64 %0, {%1, %2};" : "=l"(r) : "f"(lo), "f"(hi));
    return r;
}
__device__ __forceinline__ void unpack2(unsigned long long v, float& lo, float& hi) {
    asm("mov.b64 {%0, %1}, %2;" : "=f"(lo), "=f"(hi) : "l"(v));
}
__device__ __forceinline__ void ffma2(unsigned long long& d, unsigned long long a,
                                      unsigned long long b) {
    asm("fma.rn.f32x2 %0, %1, %2, %0;" : "+l"(d) : "l"(a), "l"(b));
}

// ---------------------------------------------------------------------------
// apply: out[r] = x[r] @ M^T + c, TMA-bulk pipelined (R6 structure) with
// packed f32x2 FMA: P0=(o0,o2) consumes (a,b)-packs against (Mj0,Mj2)-packs,
// P1=(o1,o3) against (Mj1,Mj3). 5-lane groups share a pair via LDS broadcast.
// ---------------------------------------------------------------------------
#define TPB 256
#define NSTAGE 5
#define STAGE_PAIRS 240                      // 8 warps x 30 pairs
#define STAGE_FLOATS (STAGE_PAIRS * 20)      // 19200 B
#define BAR_FLOATS 256
#define APPLY_SMEM ((BAR_FLOATS + NSTAGE * STAGE_FLOATS) * 4)

__global__ void __launch_bounds__(TPB, 2) apply_kernel(const float* __restrict__ x,
                                                       float* __restrict__ out,
                                                       long long pairs,
                                                       long long rows) {
    extern __shared__ float SH[];
    const int tid = threadIdx.x;

    unsigned bar[NSTAGE];
    #pragma unroll
    for (int s = 0; s < NSTAGE; ++s) bar[s] = smem_u32(&SH[s * 2]);

    if (tid == 0) {
        #pragma unroll
        for (int s = 0; s < NSTAGE; ++s) mbar_init(bar[s], 1);
    }
    __syncthreads();

    const long long tiles   = (pairs + STAGE_PAIRS - 1) / STAGE_PAIRS;
    const long long gstride = gridDim.x;
    const long long cta     = blockIdx.x;

    // Prologue: fill all stages.
    if (tid == 0) {
        #pragma unroll
        for (int s = 0; s < NSTAGE; ++s) {
            const long long t = cta + (long long)s * gstride;
            if (t < tiles) {
                const long long pbase = t * STAGE_PAIRS;
                const unsigned np = (unsigned)((pairs - pbase < STAGE_PAIRS)
                                                 ? (pairs - pbase) : STAGE_PAIRS);
                mbar_expect_tx(bar[s], np * 80u);
                bulk_load(smem_u32(&SH[BAR_FLOATS + s * STAGE_FLOATS]),
                          x + pbase * 20, np * 80u, bar[s]);
            }
        }
    }

    // Per-lane constants. phase = lane%5 decides the 4 output floats.
    const int lane  = tid & 31;
    const int warp  = tid >> 5;
    const int phase = lane % 5;
    const int lp    = lane / 5;              // 5-lane group (0..5; 6 -> inactive)
    const bool active = (lane < 30);
    const int offA = (phase >= 3) ? 10 : 0;  // source row for outputs w=0,1
    const int offB = (phase >= 2) ? 10 : 0;  // source row for outputs w=2,3

    // Packed M rows: Mp0[k] = (M[j0][k], M[j2][k]); Mp1[k] = (M[j1][k], M[j3][k]).
    const int j0 = (4 * phase + 0) % 10;
    const int j1 = (4 * phase + 1) % 10;
    const int j2 = (4 * phase + 2) % 10;
    const int j3 = (4 * phase + 3) % 10;
    unsigned long long Mp0[10], Mp1[10], Pc0, Pc1;
    #pragma unroll
    for (int k = 0; k < 10; ++k) {
        Mp0[k] = pack2(__ldg(&g_M3[j0 * 10 + k]), __ldg(&g_M3[j2 * 10 + k]));
        Mp1[k] = pack2(__ldg(&g_M3[j1 * 10 + k]), __ldg(&g_M3[j3 * 10 + k]));
    }
    Pc0 = pack2(__ldg(&g_c3[j0]), __ldg(&g_c3[j2]));
    Pc1 = pack2(__ldg(&g_c3[j1]), __ldg(&g_c3[j3]));

    float4* out4 = (float4*)out;

    long long i = 0;
    #pragma unroll 1
    for (long long t = cta; t < tiles; t += gstride, ++i) {
        const int s = (int)(i % NSTAGE);
        const unsigned parity = (unsigned)((i / NSTAGE) & 1);
        mbar_wait(bar[s], parity);

        const float* st = &SH[BAR_FLOATS + s * STAGE_FLOATS];
        const long long tb = t * STAGE_PAIRS;

        #pragma unroll
        for (int it = 0; it < 5; ++it) {
            const int p = warp * 30 + it * 6 + lp;
            const long long gp = tb + p;
            if (active && gp < pairs) {
                const float2* rA = (const float2*)(st + p * 20 + offA);
                const float2* rB = (const float2*)(st + p * 20 + offB);
                unsigned long long P0 = Pc0, P1 = Pc1;
                #pragma unroll
                for (int kk = 0; kk < 5; ++kk) {
                    const float2 a = rA[kk];
                    const float2 b = rB[kk];
                    const unsigned long long abx = pack2(a.x, b.x);
                    const unsigned long long aby = pack2(a.y, b.y);
                    ffma2(P0, Mp0[2 * kk],     abx);
                    ffma2(P1, Mp1[2 * kk],     abx);
                    ffma2(P0, Mp0[2 * kk + 1], aby);
                    ffma2(P1, Mp1[2 * kk + 1], aby);
                }
                float o0, o1, o2, o3;
                unpack2(P0, o0, o2);
                unpack2(P1, o1, o3);
                out4[gp * 5 + phase] = make_float4(o0, o1, o2, o3);
            }
        }

        __syncthreads();   // all warps done reading stage s
        const long long tn = t + (long long)NSTAGE * gstride;
        if (tn < tiles && tid == 0) {
            const long long pbase = tn * STAGE_PAIRS;
            const unsigned np = (unsigned)((pairs - pbase < STAGE_PAIRS)
                                             ? (pairs - pbase) : STAGE_PAIRS);
            mbar_expect_tx(bar[s], np * 80u);
            bulk_load(smem_u32(&SH[BAR_FLOATS + s * STAGE_FLOATS]),
                      x + pbase * 20, np * 80u, bar[s]);
        }
    }

    // Odd-row tail (rows is even for this problem; kept for safety).
    if ((rows & 1LL) && blockIdx.x == 0 && tid == 0) {
        const long long r = rows - 1;
        const float* xr = x + r * 10;
        float h[10];
        #pragma unroll
        for (int k = 0; k < 10; ++k) h[k] = xr[k];
        float* orow = out + r * 10;
        #pragma unroll
        for (int j = 0; j < 10; ++j) {
            float a = __ldg(&g_c3[j]);
            #pragma unroll
            for (int k = 0; k < 10; ++k) a += h[k] * __ldg(&g_M3[j * 10 + k]);
            orow[j] = a;
        }
    }
}

extern "C" void kernel_launch(void* const* d_in, const int* in_sizes, int n_in,
                              void* d_out, int out_size) {
    // Identify inputs by element count: x=BATCH*10, Ws=1000*100, bs=1000*10.
    const float* x  = nullptr;
    const float* Ws = nullptr;
    const float* bs = nullptr;
    long long x_elems = 0;
    for (int i = 0; i < n_in; ++i) {
        if (in_sizes[i] == 1000 * 100) {
            Ws = (const float*)d_in[i];
        } else if (in_sizes[i] == 1000 * 10) {
            bs = (const float*)d_in[i];
        } else {
            x = (const float*)d_in[i];
            x_elems = in_sizes[i];
        }
    }
    const long long rows  = x_elems / 10;
    const long long pairs = rows >> 1;

    // Node 1: compose 1000 affines -> 1 (13 CTAs, internal counter handshake).
    fold_kernel<<<13, 256>>>(Ws, bs);

    // Node 2: TMA-pipelined streaming apply (296 CTAs = 2/SM, 97KB smem each).
    static int smem_set = 0;
    if (!smem_set) {
        cudaFuncSetAttribute(apply_kernel,
                             cudaFuncAttributeMaxDynamicSharedMemorySize, APPLY_SMEM);
        smem_set = 1;
    }
    apply_kernel<<<296, TPB, APPLY_SMEM>>>(x, (float*)d_out, pairs, rows);
}